// round 1
// baseline (speedup 1.0000x reference)
#include <cuda_runtime.h>
#include <math.h>

#define S 2048
#define H 2048
#define NH 16
#define D 128
#define NE 8
#define TOPK 4
#define IE 1408
#define IS 5632

// ---------------- scratch (device globals: sanctioned workaround) ----------------
static __device__ float g_h1[S * H];
static __device__ float g_q[S * H];
static __device__ float g_k[S * H];
static __device__ float g_v[S * H];
static __device__ float g_sc[(long long)NH * S * S];
static __device__ float g_at[S * H];
static __device__ float g_x2[S * H];
static __device__ float g_h2[S * H];
static __device__ float g_w[NE * S];
static __device__ float g_gb[(long long)NE * S * IE];
static __device__ float g_ub[(long long)NE * S * IE];
static __device__ float g_eo[(long long)NE * S * H];
static __device__ float g_sgb[(long long)S * IS];
static __device__ float g_sub[(long long)S * IS];
static __device__ float g_sm[S * H];
static __device__ float g_sgl[S];
static __device__ float g_rl[S * NE];

// ---------------- generic tiled SGEMM ----------------
// C[M,N] = A[M,K] * B  (+ epilogue). Row-major everywhere.
// TB=false: B is K x N (ldb = row stride). TB=true: B is N x K, we compute A*B^T.
// EPI: 0 = store, 1 = store + bias[col], 2 = store + resid[row,col]
// blockIdx.z batches via byte-element strides sA/sB/sC.
template <bool TB, int EPI>
__global__ void __launch_bounds__(256, 2)
sgemm_kernel(const float* __restrict__ A, const float* __restrict__ B,
             float* __restrict__ C, const float* __restrict__ X,
             int M, int N, int K, int lda, int ldb, int ldc,
             long long sA, long long sB, long long sC) {
    __shared__ float As[16][128];
    __shared__ float Bs[16][128];
    int bx = blockIdx.x, by = blockIdx.y, bz = blockIdx.z;
    A += (long long)bz * sA;
    B += (long long)bz * sB;
    C += (long long)bz * sC;
    int tid = threadIdx.x;
    int tx = tid & 15, ty = tid >> 4;
    int row0 = by * 128, col0 = bx * 128;

    float acc[8][8];
#pragma unroll
    for (int i = 0; i < 8; i++)
#pragma unroll
        for (int j = 0; j < 8; j++) acc[i][j] = 0.f;

    for (int k0 = 0; k0 < K; k0 += 16) {
        // A tile 128x16, stored transposed As[k][m]
#pragma unroll
        for (int i = 0; i < 2; i++) {
            int f = tid + i * 256;
            int r = f >> 2, c = (f & 3) * 4;
            float4 val = *(const float4*)&A[(long long)(row0 + r) * lda + k0 + c];
            As[c + 0][r] = val.x; As[c + 1][r] = val.y;
            As[c + 2][r] = val.z; As[c + 3][r] = val.w;
        }
        if (TB) {
            // B' tile: 128 (n) x 16 (k) -> Bs[k][n]
#pragma unroll
            for (int i = 0; i < 2; i++) {
                int f = tid + i * 256;
                int r = f >> 2, c = (f & 3) * 4;
                float4 val = *(const float4*)&B[(long long)(col0 + r) * ldb + k0 + c];
                Bs[c + 0][r] = val.x; Bs[c + 1][r] = val.y;
                Bs[c + 2][r] = val.z; Bs[c + 3][r] = val.w;
            }
        } else {
            // B tile: 16 (k) x 128 (n)
#pragma unroll
            for (int i = 0; i < 2; i++) {
                int f = tid + i * 256;
                int r = f >> 5, c = (f & 31) * 4;
                *(float4*)&Bs[r][c] =
                    *(const float4*)&B[(long long)(k0 + r) * ldb + col0 + c];
            }
        }
        __syncthreads();
#pragma unroll
        for (int kk = 0; kk < 16; kk++) {
            float a[8], b[8];
#pragma unroll
            for (int i = 0; i < 8; i++) a[i] = As[kk][ty * 8 + i];
#pragma unroll
            for (int j = 0; j < 8; j++) b[j] = Bs[kk][tx * 8 + j];
#pragma unroll
            for (int i = 0; i < 8; i++)
#pragma unroll
                for (int j = 0; j < 8; j++) acc[i][j] += a[i] * b[j];
        }
        __syncthreads();
    }
#pragma unroll
    for (int i = 0; i < 8; i++) {
        int r = row0 + ty * 8 + i;
#pragma unroll
        for (int j = 0; j < 8; j += 4) {
            int c = col0 + tx * 8 + j;
            float4 o;
            o.x = acc[i][j]; o.y = acc[i][j + 1];
            o.z = acc[i][j + 2]; o.w = acc[i][j + 3];
            if (EPI == 1) {
                o.x += X[c]; o.y += X[c + 1]; o.z += X[c + 2]; o.w += X[c + 3];
            }
            if (EPI == 2) {
                float4 rr = *(const float4*)&X[(long long)r * ldc + c];
                o.x += rr.x; o.y += rr.y; o.z += rr.z; o.w += rr.w;
            }
            *(float4*)&C[(long long)r * ldc + c] = o;
        }
    }
}

// ---------------- RMSNorm ----------------
__global__ void rmsnorm_kernel(const float* __restrict__ x, const float* __restrict__ w,
                               float* __restrict__ o) {
    int s = blockIdx.x;
    const float* xr = x + (long long)s * H;
    float* orow = o + (long long)s * H;
    int tid = threadIdx.x;
    float ss = 0.f;
    for (int i = tid; i < H; i += 256) { float v = xr[i]; ss += v * v; }
    __shared__ float sh[8];
#pragma unroll
    for (int off = 16; off; off >>= 1) ss += __shfl_xor_sync(0xffffffffu, ss, off);
    if ((tid & 31) == 0) sh[tid >> 5] = ss;
    __syncthreads();
    ss = sh[tid & 7];
#pragma unroll
    for (int off = 4; off; off >>= 1) ss += __shfl_xor_sync(0xffffffffu, ss, off);
    float inv = rsqrtf(ss / (float)H + 1e-6f);
    for (int i = tid; i < H; i += 256) orow[i] = w[i] * xr[i] * inv;
}

// ---------------- RoPE (in-place on q and k) ----------------
__global__ void rope_kernel(float* __restrict__ q, float* __restrict__ k) {
    int s = blockIdx.x, h = blockIdx.y, d = threadIdx.x;  // d in [0,64)
    double invd = exp(-((double)(2 * d) / 128.0) * 13.815510557964274);  // ln(1e6)
    float inv = (float)invd;
    float ang = (float)s * inv;
    float c = cosf(ang), sn = sinf(ang);
    long long base = ((long long)s * NH + h) * D;
    float q1 = q[base + d], q2 = q[base + d + 64];
    q[base + d] = q1 * c - q2 * sn;
    q[base + d + 64] = q2 * c + q1 * sn;
    float k1 = k[base + d], k2 = k[base + d + 64];
    k[base + d] = k1 * c - k2 * sn;
    k[base + d + 64] = k2 * c + k1 * sn;
}

// ---------------- causal softmax (scale folded in) ----------------
__global__ void softmax_causal_kernel(float* __restrict__ sc) {
    long long row = blockIdx.x;           // h*S + q
    int q = (int)(row & (S - 1));
    float* p = sc + row * S;
    int n = q + 1;
    int tid = threadIdx.x;
    __shared__ float sh[8];
    const float scale = 0.08838834764831845f;  // 1/sqrt(128)
    float mx = -3.4e38f;
    for (int i = tid; i < n; i += 256) mx = fmaxf(mx, p[i]);
#pragma unroll
    for (int o = 16; o; o >>= 1) mx = fmaxf(mx, __shfl_xor_sync(0xffffffffu, mx, o));
    if ((tid & 31) == 0) sh[tid >> 5] = mx;
    __syncthreads();
    mx = sh[tid & 7];
#pragma unroll
    for (int o = 4; o; o >>= 1) mx = fmaxf(mx, __shfl_xor_sync(0xffffffffu, mx, o));
    __syncthreads();
    float sum = 0.f;
    for (int i = tid; i < n; i += 256) {
        float e = expf((p[i] - mx) * scale);
        p[i] = e;
        sum += e;
    }
#pragma unroll
    for (int o = 16; o; o >>= 1) sum += __shfl_xor_sync(0xffffffffu, sum, o);
    if ((tid & 31) == 0) sh[tid >> 5] = sum;
    __syncthreads();
    sum = sh[tid & 7];
#pragma unroll
    for (int o = 4; o; o >>= 1) sum += __shfl_xor_sync(0xffffffffu, sum, o);
    float inv = 1.f / sum;
    for (int i = tid; i < S; i += 256) p[i] = (i < n) ? p[i] * inv : 0.f;
}

// ---------------- router + top-k + sgate dot ----------------
__global__ void router_kernel(const float* __restrict__ h2, const float* __restrict__ gw,
                              const float* __restrict__ sgate, float* __restrict__ rl,
                              float* __restrict__ wexp, float* __restrict__ sgl) {
    int s = blockIdx.x;
    int tid = threadIdx.x;
    const float* hr = h2 + (long long)s * H;
    float acc[9];
#pragma unroll
    for (int j = 0; j < 9; j++) acc[j] = 0.f;
    for (int i = tid; i < H; i += 256) {
        float hv = hr[i];
        const float* gr = gw + (long long)i * NE;
#pragma unroll
        for (int e = 0; e < NE; e++) acc[e] += hv * gr[e];
        acc[8] += hv * sgate[i];
    }
    __shared__ float sh[8][9];
    int warp = tid >> 5, lane = tid & 31;
#pragma unroll
    for (int j = 0; j < 9; j++) {
        float v = acc[j];
#pragma unroll
        for (int o = 16; o; o >>= 1) v += __shfl_xor_sync(0xffffffffu, v, o);
        if (lane == 0) sh[warp][j] = v;
    }
    __syncthreads();
    if (tid == 0) {
        float t[9];
#pragma unroll
        for (int j = 0; j < 9; j++) {
            float v = 0.f;
            for (int wi = 0; wi < 8; wi++) v += sh[wi][j];
            t[j] = v;
        }
        float mx = t[0];
        for (int e = 1; e < NE; e++) mx = fmaxf(mx, t[e]);
        float p[NE], sum = 0.f;
        for (int e = 0; e < NE; e++) { p[e] = expf(t[e] - mx); sum += p[e]; }
        for (int e = 0; e < NE; e++) p[e] /= sum;
        float w8[NE];
        for (int e = 0; e < NE; e++) w8[e] = 0.f;
        for (int tI = 0; tI < TOPK; tI++) {
            int bi = 0;
            float bv = p[0];
            for (int e = 1; e < NE; e++)
                if (p[e] > bv) { bv = p[e]; bi = e; }
            w8[bi] = bv;
            p[bi] = -1.f;
        }
        for (int e = 0; e < NE; e++) {
            wexp[e * S + s] = w8[e];
            rl[s * NE + e] = t[e];
        }
        sgl[s] = t[8];
    }
}

// ---------------- silu(g)*u elementwise ----------------
__global__ void silumul_kernel(const float* __restrict__ g, const float* __restrict__ u,
                               float* __restrict__ o, long long n) {
    long long i = (long long)blockIdx.x * 256 + threadIdx.x;
    if (i < n) {
        float x = g[i];
        o[i] = (x / (1.f + expf(-x))) * u[i];
    }
}

// ---------------- final combine ----------------
__global__ void final_kernel(const float* __restrict__ x2, const float* __restrict__ eo,
                             const float* __restrict__ wexp, const float* __restrict__ sm,
                             const float* __restrict__ sgl, float* __restrict__ out) {
    int i = blockIdx.x * 256 + threadIdx.x;  // < S*H exactly
    int s = i >> 11;                          // H = 2048
    float mo = 0.f;
#pragma unroll
    for (int e = 0; e < NE; e++) mo += wexp[e * S + s] * eo[(long long)e * S * H + i];
    float gg = 1.f / (1.f + expf(-sgl[s]));
    out[i] = x2[i] + mo + gg * sm[i];
}

// ---------------- host orchestration ----------------
extern "C" void kernel_launch(void* const* d_in, const int* in_sizes, int n_in,
                              void* d_out, int out_size) {
    const float* x = (const float*)d_in[0];
    const float* ln1 = (const float*)d_in[1];
    const float* ln2 = (const float*)d_in[2];
    const float* wq = (const float*)d_in[3];
    const float* bq = (const float*)d_in[4];
    const float* wk = (const float*)d_in[5];
    const float* bk = (const float*)d_in[6];
    const float* wv = (const float*)d_in[7];
    const float* bv = (const float*)d_in[8];
    const float* wo = (const float*)d_in[9];
    const float* gw = (const float*)d_in[10];
    const float* eg = (const float*)d_in[11];
    const float* eu = (const float*)d_in[12];
    const float* ed = (const float*)d_in[13];
    const float* sg = (const float*)d_in[14];
    const float* su = (const float*)d_in[15];
    const float* sd = (const float*)d_in[16];
    const float* sgate = (const float*)d_in[17];
    float* out = (float*)d_out;

    float *h1, *q, *k, *v, *sc, *at, *x2, *h2, *wexp, *gb, *ub, *eo, *sgb, *sub, *sm, *sgl, *rls;
    cudaGetSymbolAddress((void**)&h1, g_h1);
    cudaGetSymbolAddress((void**)&q, g_q);
    cudaGetSymbolAddress((void**)&k, g_k);
    cudaGetSymbolAddress((void**)&v, g_v);
    cudaGetSymbolAddress((void**)&sc, g_sc);
    cudaGetSymbolAddress((void**)&at, g_at);
    cudaGetSymbolAddress((void**)&x2, g_x2);
    cudaGetSymbolAddress((void**)&h2, g_h2);
    cudaGetSymbolAddress((void**)&wexp, g_w);
    cudaGetSymbolAddress((void**)&gb, g_gb);
    cudaGetSymbolAddress((void**)&ub, g_ub);
    cudaGetSymbolAddress((void**)&eo, g_eo);
    cudaGetSymbolAddress((void**)&sgb, g_sgb);
    cudaGetSymbolAddress((void**)&sub, g_sub);
    cudaGetSymbolAddress((void**)&sm, g_sm);
    cudaGetSymbolAddress((void**)&sgl, g_sgl);
    cudaGetSymbolAddress((void**)&rls, g_rl);

    // router_logits destination: tail of output if it fits, else scratch
    float* rl_dst = (out_size >= S * H + S * NE) ? (out + (size_t)S * H) : rls;

    // 1) h1 = rmsnorm(x, ln1)
    rmsnorm_kernel<<<S, 256>>>(x, ln1, h1);

    // 2-4) q,k,v = h1 @ w{q,k,v} + b
    {
        dim3 grid(H / 128, S / 128, 1);
        sgemm_kernel<false, 1><<<grid, 256>>>(h1, wq, q, bq, S, H, H, H, H, H, 0, 0, 0);
        sgemm_kernel<false, 1><<<grid, 256>>>(h1, wk, k, bk, S, H, H, H, H, H, 0, 0, 0);
        sgemm_kernel<false, 1><<<grid, 256>>>(h1, wv, v, bv, S, H, H, H, H, H, 0, 0, 0);
    }

    // 5) RoPE in-place
    {
        dim3 grid(S, NH);
        rope_kernel<<<grid, 64>>>(q, k);
    }

    // 6) scores[h] = q_h @ k_h^T   (batched NT over heads)
    {
        dim3 grid(S / 128, S / 128, NH);
        sgemm_kernel<true, 0><<<grid, 256>>>(q, k, sc, (const float*)0,
                                             S, S, D, H, H, S,
                                             (long long)D, (long long)D, (long long)S * S);
    }

    // 7) causal softmax (scale folded)
    softmax_causal_kernel<<<NH * S, 256>>>(sc);

    // 8) at[h] = probs_h @ v_h     (batched NN over heads)
    {
        dim3 grid(D / 128, S / 128, NH);
        sgemm_kernel<false, 0><<<grid, 256>>>(sc, v, at, (const float*)0,
                                              S, D, S, S, H, H,
                                              (long long)S * S, (long long)D, (long long)D);
    }

    // 9) x2 = x + at @ wo
    {
        dim3 grid(H / 128, S / 128, 1);
        sgemm_kernel<false, 2><<<grid, 256>>>(at, wo, x2, x, S, H, H, H, H, H, 0, 0, 0);
    }

    // 10) h2 = rmsnorm(x2, ln2)
    rmsnorm_kernel<<<S, 256>>>(x2, ln2, h2);

    // 11) router logits, softmax/top-4 weights, sgate dot
    router_kernel<<<S, 256>>>(h2, gw, sgate, rl_dst, wexp, sgl);

    // 12-14) dense MoE: g/u GEMMs batched over experts, silu*u, down GEMM
    {
        dim3 grid(IE / 128, S / 128, NE);
        sgemm_kernel<false, 0><<<grid, 256>>>(h2, eg, gb, (const float*)0,
                                              S, IE, H, H, IE, IE,
                                              0LL, (long long)H * IE, (long long)S * IE);
        sgemm_kernel<false, 0><<<grid, 256>>>(h2, eu, ub, (const float*)0,
                                              S, IE, H, H, IE, IE,
                                              0LL, (long long)H * IE, (long long)S * IE);
    }
    {
        long long n = (long long)NE * S * IE;
        silumul_kernel<<<(unsigned)((n + 255) / 256), 256>>>(gb, ub, gb, n);
    }
    {
        dim3 grid(H / 128, S / 128, NE);
        sgemm_kernel<false, 0><<<grid, 256>>>(gb, ed, eo, (const float*)0,
                                              S, H, IE, IE, H, H,
                                              (long long)S * IE, (long long)IE * H,
                                              (long long)S * H);
    }

    // 15-18) shared MLP
    {
        dim3 grid(IS / 128, S / 128, 1);
        sgemm_kernel<false, 0><<<grid, 256>>>(h2, sg, sgb, (const float*)0,
                                              S, IS, H, H, IS, IS, 0, 0, 0);
        sgemm_kernel<false, 0><<<grid, 256>>>(h2, su, sub, (const float*)0,
                                              S, IS, H, H, IS, IS, 0, 0, 0);
    }
    {
        long long n = (long long)S * IS;
        silumul_kernel<<<(unsigned)((n + 255) / 256), 256>>>(sgb, sub, sgb, n);
    }
    {
        dim3 grid(H / 128, S / 128, 1);
        sgemm_kernel<false, 0><<<grid, 256>>>(sgb, sd, sm, (const float*)0,
                                              S, H, IS, IS, H, H, 0, 0, 0);
    }

    // 19) out = x2 + sum_e w[e]*eo[e] + sigmoid(sgl)*sm
    final_kernel<<<(S * H) / 256, 256>>>(x2, eo, wexp, sm, sgl, out);
}

// round 3
// speedup vs baseline: 4.7705x; 4.7705x over previous
#include <cuda_runtime.h>
#include <cstdint>
#include <math.h>

#define S 2048
#define H 2048
#define NH 16
#define D 128
#define NE 8
#define TOPK 4
#define IE 1408
#define IS 5632

// ---------------- scratch ----------------
static __device__ float g_h1[S * H];
static __device__ float g_q[S * H];
static __device__ float g_k[S * H];
static __device__ float g_v[S * H];
static __device__ float g_sc[(long long)NH * S * S];
static __device__ float g_at[S * H];
static __device__ float g_x2[S * H];
static __device__ float g_h2[S * H];
static __device__ float g_w[NE * S];
static __device__ float g_gb[(long long)NE * S * IE];
static __device__ float g_ub[(long long)NE * S * IE];
static __device__ float g_eo[(long long)NE * S * H];
static __device__ float g_sgb[(long long)S * IS];
static __device__ float g_sub[(long long)S * IS];
static __device__ float g_sm[S * H];
static __device__ float g_sgl[S];
static __device__ float g_rl[S * NE];

// ---------------- helpers ----------------
__device__ __forceinline__ uint32_t smem_u32(const void* p) {
    uint32_t a;
    asm("{ .reg .u64 t; cvta.to.shared.u64 t, %1; cvt.u32.u64 %0, t; }" : "=r"(a) : "l"(p));
    return a;
}
__device__ __forceinline__ uint32_t rna_tf32(float x) {
    uint32_t u;
    asm("cvt.rna.tf32.f32 %0, %1;" : "=r"(u) : "f"(x));
    return u;
}
__device__ __forceinline__ void cp16(uint32_t dst, const void* src) {
    asm volatile("cp.async.cg.shared.global [%0], [%1], 16;" :: "r"(dst), "l"(src));
}
#define CP_COMMIT() asm volatile("cp.async.commit_group;" ::: "memory")
#define CP_WAIT1() asm volatile("cp.async.wait_group 1;" ::: "memory")
#define CP_WAIT0() asm volatile("cp.async.wait_group 0;" ::: "memory")

__device__ __forceinline__ void mma_tf32(float* d, const uint32_t* a, const uint32_t* b) {
    asm volatile(
        "mma.sync.aligned.m16n8k8.row.col.f32.tf32.tf32.f32 "
        "{%0,%1,%2,%3}, {%4,%5,%6,%7}, {%8,%9}, {%0,%1,%2,%3};"
        : "+f"(d[0]), "+f"(d[1]), "+f"(d[2]), "+f"(d[3])
        : "r"(a[0]), "r"(a[1]), "r"(a[2]), "r"(a[3]), "r"(b[0]), "r"(b[1]));
}

// ---------------- tf32 mma.sync GEMM ----------------
// C[M,N] = A[M,K] @ B (+ epilogue).
// TB=false: B is [K][N] row-major (ldb). TB=true: B is [N][K] row-major (ldb), compute A@B^T.
// EPI: 0 none, 1 +bias[col], 2 +resid[row][col] (stride ldc).
// CMODE: 0 none, 1 causal tile skip, 2 causal K-trim.
template <bool TB, int EPI, int CMODE>
__global__ void __launch_bounds__(256, 2)
mma_gemm(const float* __restrict__ A, const float* __restrict__ B,
         float* __restrict__ C, const float* __restrict__ X,
         int K, int lda, int ldb, int ldc,
         long long sA, long long sB, long long sC) {
    if (CMODE == 1 && blockIdx.x > blockIdx.y) return;

    constexpr int BROWS = TB ? 128 : 16;
    constexpr int BCOLS = TB ? 20 : 132;
    __shared__ __align__(16) float As[2][128][20];
    __shared__ __align__(16) float Bs[2][BROWS][BCOLS];

    int tid = threadIdx.x, lane = tid & 31, wid = tid >> 5;
    int row0 = blockIdx.y * 128, col0 = blockIdx.x * 128;

    A += (long long)blockIdx.z * sA + (long long)row0 * lda;
    B += (long long)blockIdx.z * sB + (TB ? (long long)col0 * ldb : (long long)col0);
    C += (long long)blockIdx.z * sC;

    int nstg = K >> 4;
    if (CMODE == 2) { int lim = (blockIdx.y + 1) * 8; if (lim < nstg) nstg = lim; }

    int arow = tid >> 2, acol = (tid & 3) * 4;         // A/B-NT fill mapping (x2)
    int brow = tid >> 5, bcol = (tid & 31) * 4;        // B-NN fill mapping (x2)

    auto loadA = [&](int buf, int k0) {
#pragma unroll
        for (int i = 0; i < 2; i++) {
            int r = arow + i * 64;
            cp16(smem_u32(&As[buf][r][acol]), A + (long long)r * lda + k0 + acol);
        }
    };
    auto loadB = [&](int buf, int k0) {
        if (TB) {
#pragma unroll
            for (int i = 0; i < 2; i++) {
                int r = arow + i * 64;
                cp16(smem_u32(&Bs[buf][r][acol]), B + (long long)r * ldb + k0 + acol);
            }
        } else {
#pragma unroll
            for (int i = 0; i < 2; i++) {
                int r = brow + i * 8;
                cp16(smem_u32(&Bs[buf][r][bcol]), B + (long long)(k0 + r) * ldb + bcol);
            }
        }
    };

    float acc[4][4][4];
#pragma unroll
    for (int i = 0; i < 4; i++)
#pragma unroll
        for (int j = 0; j < 4; j++)
#pragma unroll
            for (int u = 0; u < 4; u++) acc[i][j][u] = 0.f;

    int wm = (wid & 1) * 64, wn = (wid >> 1) * 32;
    int fr = lane >> 2, fc = lane & 3;

    loadA(0, 0); loadB(0, 0); CP_COMMIT();

    for (int t = 0; t < nstg; t++) {
        if (t + 1 < nstg) {
            loadA((t + 1) & 1, (t + 1) * 16);
            loadB((t + 1) & 1, (t + 1) * 16);
            CP_COMMIT();
            CP_WAIT1();
        } else {
            CP_WAIT0();
        }
        __syncthreads();
        int buf = t & 1;
#pragma unroll
        for (int kk = 0; kk < 16; kk += 8) {
            uint32_t af[4][4];
#pragma unroll
            for (int mt = 0; mt < 4; mt++) {
                const float* ap = &As[buf][wm + mt * 16 + fr][kk + fc];
                af[mt][0] = rna_tf32(ap[0]);
                af[mt][1] = rna_tf32(ap[8 * 20]);
                af[mt][2] = rna_tf32(ap[4]);
                af[mt][3] = rna_tf32(ap[8 * 20 + 4]);
            }
            uint32_t bf[4][2];
#pragma unroll
            for (int nt = 0; nt < 4; nt++) {
                if (TB) {
                    const float* bp = &Bs[buf][wn + nt * 8 + fr][kk + fc];
                    bf[nt][0] = rna_tf32(bp[0]);
                    bf[nt][1] = rna_tf32(bp[4]);
                } else {
                    const float* bp = &Bs[buf][kk + fc][wn + nt * 8 + fr];
                    bf[nt][0] = rna_tf32(bp[0]);
                    bf[nt][1] = rna_tf32(bp[4 * 132]);
                }
            }
#pragma unroll
            for (int mt = 0; mt < 4; mt++)
#pragma unroll
                for (int nt = 0; nt < 4; nt++) mma_tf32(acc[mt][nt], af[mt], bf[nt]);
        }
        __syncthreads();
    }

    // epilogue
#pragma unroll
    for (int mt = 0; mt < 4; mt++) {
        int m = row0 + wm + mt * 16 + fr;
#pragma unroll
        for (int nt = 0; nt < 4; nt++) {
            int n = col0 + wn + nt * 8 + fc * 2;
            float2 v0 = make_float2(acc[mt][nt][0], acc[mt][nt][1]);
            float2 v1 = make_float2(acc[mt][nt][2], acc[mt][nt][3]);
            if (EPI == 1) {
                v0.x += X[n]; v0.y += X[n + 1];
                v1.x += X[n]; v1.y += X[n + 1];
            }
            if (EPI == 2) {
                const float2 r0 = *(const float2*)&X[(long long)m * ldc + n];
                const float2 r1 = *(const float2*)&X[(long long)(m + 8) * ldc + n];
                v0.x += r0.x; v0.y += r0.y;
                v1.x += r1.x; v1.y += r1.y;
            }
            *(float2*)&C[(long long)m * ldc + n] = v0;
            *(float2*)&C[(long long)(m + 8) * ldc + n] = v1;
        }
    }
}

// ---------------- RMSNorm ----------------
__global__ void rmsnorm_kernel(const float* __restrict__ x, const float* __restrict__ w,
                               float* __restrict__ o) {
    int s = blockIdx.x;
    const float* xr = x + (long long)s * H;
    float* orow = o + (long long)s * H;
    int tid = threadIdx.x;
    float ss = 0.f;
    for (int i = tid; i < H; i += 256) { float v = xr[i]; ss += v * v; }
    __shared__ float sh[8];
#pragma unroll
    for (int off = 16; off; off >>= 1) ss += __shfl_xor_sync(0xffffffffu, ss, off);
    if ((tid & 31) == 0) sh[tid >> 5] = ss;
    __syncthreads();
    ss = sh[tid & 7];
#pragma unroll
    for (int off = 4; off; off >>= 1) ss += __shfl_xor_sync(0xffffffffu, ss, off);
    float inv = rsqrtf(ss / (float)H + 1e-6f);
    for (int i = tid; i < H; i += 256) orow[i] = w[i] * xr[i] * inv;
}

// ---------------- RoPE ----------------
__global__ void rope_kernel(float* __restrict__ q, float* __restrict__ k) {
    int s = blockIdx.x, h = blockIdx.y, d = threadIdx.x;  // d in [0,64)
    double invd = exp(-((double)(2 * d) / 128.0) * 13.815510557964274);
    float inv = (float)invd;
    float ang = (float)s * inv;
    float c = cosf(ang), sn = sinf(ang);
    long long base = ((long long)s * NH + h) * D;
    float q1 = q[base + d], q2 = q[base + d + 64];
    q[base + d] = q1 * c - q2 * sn;
    q[base + d + 64] = q2 * c + q1 * sn;
    float k1 = k[base + d], k2 = k[base + d + 64];
    k[base + d] = k1 * c - k2 * sn;
    k[base + d + 64] = k2 * c + k1 * sn;
}

// ---------------- causal softmax ----------------
__global__ void softmax_causal_kernel(float* __restrict__ sc) {
    long long row = blockIdx.x;
    int q = (int)(row & (S - 1));
    float* p = sc + row * S;
    int n = q + 1;
    int tid = threadIdx.x;
    __shared__ float sh[8];
    const float scale = 0.08838834764831845f;
    float mx = -3.4e38f;
    for (int i = tid; i < n; i += 256) mx = fmaxf(mx, p[i]);
#pragma unroll
    for (int o = 16; o; o >>= 1) mx = fmaxf(mx, __shfl_xor_sync(0xffffffffu, mx, o));
    if ((tid & 31) == 0) sh[tid >> 5] = mx;
    __syncthreads();
    mx = sh[tid & 7];
#pragma unroll
    for (int o = 4; o; o >>= 1) mx = fmaxf(mx, __shfl_xor_sync(0xffffffffu, mx, o));
    __syncthreads();
    float sum = 0.f;
    for (int i = tid; i < n; i += 256) {
        float e = expf((p[i] - mx) * scale);
        p[i] = e;
        sum += e;
    }
#pragma unroll
    for (int o = 16; o; o >>= 1) sum += __shfl_xor_sync(0xffffffffu, sum, o);
    if ((tid & 31) == 0) sh[tid >> 5] = sum;
    __syncthreads();
    sum = sh[tid & 7];
#pragma unroll
    for (int o = 4; o; o >>= 1) sum += __shfl_xor_sync(0xffffffffu, sum, o);
    float inv = 1.f / sum;
    for (int i = tid; i < S; i += 256) p[i] = (i < n) ? p[i] * inv : 0.f;
}

// ---------------- router ----------------
__global__ void router_kernel(const float* __restrict__ h2, const float* __restrict__ gw,
                              const float* __restrict__ sgate, float* __restrict__ rl,
                              float* __restrict__ wexp, float* __restrict__ sgl) {
    int s = blockIdx.x;
    int tid = threadIdx.x;
    const float* hr = h2 + (long long)s * H;
    float acc[9];
#pragma unroll
    for (int j = 0; j < 9; j++) acc[j] = 0.f;
    for (int i = tid; i < H; i += 256) {
        float hv = hr[i];
        const float* gr = gw + (long long)i * NE;
#pragma unroll
        for (int e = 0; e < NE; e++) acc[e] += hv * gr[e];
        acc[8] += hv * sgate[i];
    }
    __shared__ float sh[8][9];
    int warp = tid >> 5, lane = tid & 31;
#pragma unroll
    for (int j = 0; j < 9; j++) {
        float v = acc[j];
#pragma unroll
        for (int o = 16; o; o >>= 1) v += __shfl_xor_sync(0xffffffffu, v, o);
        if (lane == 0) sh[warp][j] = v;
    }
    __syncthreads();
    if (tid == 0) {
        float t[9];
#pragma unroll
        for (int j = 0; j < 9; j++) {
            float v = 0.f;
            for (int wi = 0; wi < 8; wi++) v += sh[wi][j];
            t[j] = v;
        }
        float mx = t[0];
        for (int e = 1; e < NE; e++) mx = fmaxf(mx, t[e]);
        float p[NE], sum = 0.f;
        for (int e = 0; e < NE; e++) { p[e] = expf(t[e] - mx); sum += p[e]; }
        for (int e = 0; e < NE; e++) p[e] /= sum;
        float w8[NE];
        for (int e = 0; e < NE; e++) w8[e] = 0.f;
        for (int tI = 0; tI < TOPK; tI++) {
            int bi = 0;
            float bv = p[0];
            for (int e = 1; e < NE; e++)
                if (p[e] > bv) { bv = p[e]; bi = e; }
            w8[bi] = bv;
            p[bi] = -1.f;
        }
        for (int e = 0; e < NE; e++) {
            wexp[e * S + s] = w8[e];
            rl[s * NE + e] = t[e];
        }
        sgl[s] = t[8];
    }
}

// ---------------- silu(g)*u ----------------
__global__ void silumul_kernel(const float* __restrict__ g, const float* __restrict__ u,
                               float* __restrict__ o, long long n) {
    long long i = (long long)blockIdx.x * 256 + threadIdx.x;
    if (i < n) {
        float x = g[i];
        o[i] = (x / (1.f + expf(-x))) * u[i];
    }
}

// ---------------- final combine ----------------
__global__ void final_kernel(const float* __restrict__ x2, const float* __restrict__ eo,
                             const float* __restrict__ wexp, const float* __restrict__ sm,
                             const float* __restrict__ sgl, float* __restrict__ out) {
    int i = blockIdx.x * 256 + threadIdx.x;
    int s = i >> 11;
    float mo = 0.f;
#pragma unroll
    for (int e = 0; e < NE; e++) mo += wexp[e * S + s] * eo[(long long)e * S * H + i];
    float gg = 1.f / (1.f + expf(-sgl[s]));
    out[i] = x2[i] + mo + gg * sm[i];
}

// ---------------- host ----------------
extern "C" void kernel_launch(void* const* d_in, const int* in_sizes, int n_in,
                              void* d_out, int out_size) {
    const float* x = (const float*)d_in[0];
    const float* ln1 = (const float*)d_in[1];
    const float* ln2 = (const float*)d_in[2];
    const float* wq = (const float*)d_in[3];
    const float* bq = (const float*)d_in[4];
    const float* wk = (const float*)d_in[5];
    const float* bk = (const float*)d_in[6];
    const float* wv = (const float*)d_in[7];
    const float* bv = (const float*)d_in[8];
    const float* wo = (const float*)d_in[9];
    const float* gw = (const float*)d_in[10];
    const float* eg = (const float*)d_in[11];
    const float* eu = (const float*)d_in[12];
    const float* ed = (const float*)d_in[13];
    const float* sg = (const float*)d_in[14];
    const float* su = (const float*)d_in[15];
    const float* sd = (const float*)d_in[16];
    const float* sgate = (const float*)d_in[17];
    float* out = (float*)d_out;

    float *h1, *q, *k, *v, *sc, *at, *x2, *h2, *wexp, *gb, *ub, *eo, *sgb, *sub, *sm, *sgl, *rls;
    cudaGetSymbolAddress((void**)&h1, g_h1);
    cudaGetSymbolAddress((void**)&q, g_q);
    cudaGetSymbolAddress((void**)&k, g_k);
    cudaGetSymbolAddress((void**)&v, g_v);
    cudaGetSymbolAddress((void**)&sc, g_sc);
    cudaGetSymbolAddress((void**)&at, g_at);
    cudaGetSymbolAddress((void**)&x2, g_x2);
    cudaGetSymbolAddress((void**)&h2, g_h2);
    cudaGetSymbolAddress((void**)&wexp, g_w);
    cudaGetSymbolAddress((void**)&gb, g_gb);
    cudaGetSymbolAddress((void**)&ub, g_ub);
    cudaGetSymbolAddress((void**)&eo, g_eo);
    cudaGetSymbolAddress((void**)&sgb, g_sgb);
    cudaGetSymbolAddress((void**)&sub, g_sub);
    cudaGetSymbolAddress((void**)&sm, g_sm);
    cudaGetSymbolAddress((void**)&sgl, g_sgl);
    cudaGetSymbolAddress((void**)&rls, g_rl);

    float* rl_dst = (out_size >= S * H + S * NE) ? (out + (size_t)S * H) : rls;

    // 1) h1 = rmsnorm(x, ln1)
    rmsnorm_kernel<<<S, 256>>>(x, ln1, h1);

    // 2) q,k,v = h1 @ w + b   (NN, bias epilogue)
    {
        dim3 g(16, 16, 1);
        mma_gemm<false, 1, 0><<<g, 256>>>(h1, wq, q, bq, H, H, H, H, 0, 0, 0);
        mma_gemm<false, 1, 0><<<g, 256>>>(h1, wk, k, bk, H, H, H, H, 0, 0, 0);
        mma_gemm<false, 1, 0><<<g, 256>>>(h1, wv, v, bv, H, H, H, H, 0, 0, 0);
    }

    // 3) RoPE
    rope_kernel<<<dim3(S, NH), 64>>>(q, k);

    // 4) scores[h] = q_h @ k_h^T  (NT, causal tile skip)
    mma_gemm<true, 0, 1><<<dim3(16, 16, NH), 256>>>(
        q, k, sc, (const float*)0, D, H, H, S,
        (long long)D, (long long)D, (long long)S * S);

    // 5) softmax
    softmax_causal_kernel<<<NH * S, 256>>>(sc);

    // 6) at[h] = probs_h @ v_h  (NN, causal K-trim)
    mma_gemm<false, 0, 2><<<dim3(1, 16, NH), 256>>>(
        sc, v, at, (const float*)0, S, S, H, H,
        (long long)S * S, (long long)D, (long long)D);

    // 7) x2 = x + at @ wo  (NN, resid epilogue)
    mma_gemm<false, 2, 0><<<dim3(16, 16, 1), 256>>>(at, wo, x2, x, H, H, H, H, 0, 0, 0);

    // 8) h2 = rmsnorm(x2, ln2)
    rmsnorm_kernel<<<S, 256>>>(x2, ln2, h2);

    // 9) router
    router_kernel<<<S, 256>>>(h2, gw, sgate, rl_dst, wexp, sgl);

    // 10) dense MoE
    {
        dim3 g(IE / 128, 16, NE);
        mma_gemm<false, 0, 0><<<g, 256>>>(h2, eg, gb, (const float*)0,
            H, H, IE, IE, 0LL, (long long)H * IE, (long long)S * IE);
        mma_gemm<false, 0, 0><<<g, 256>>>(h2, eu, ub, (const float*)0,
            H, H, IE, IE, 0LL, (long long)H * IE, (long long)S * IE);
    }
    {
        long long n = (long long)NE * S * IE;
        silumul_kernel<<<(unsigned)((n + 255) / 256), 256>>>(gb, ub, gb, n);
    }
    mma_gemm<false, 0, 0><<<dim3(16, 16, NE), 256>>>(gb, ed, eo, (const float*)0,
        IE, IE, H, H, (long long)S * IE, (long long)IE * H, (long long)S * H);

    // 11) shared MLP
    {
        dim3 g(IS / 128, 16, 1);
        mma_gemm<false, 0, 0><<<g, 256>>>(h2, sg, sgb, (const float*)0, H, H, IS, IS, 0, 0, 0);
        mma_gemm<false, 0, 0><<<g, 256>>>(h2, su, sub, (const float*)0, H, H, IS, IS, 0, 0, 0);
    }
    {
        long long n = (long long)S * IS;
        silumul_kernel<<<(unsigned)((n + 255) / 256), 256>>>(sgb, sub, sgb, n);
    }
    mma_gemm<false, 0, 0><<<dim3(16, 16, 1), 256>>>(sgb, sd, sm, (const float*)0,
        IS, IS, H, H, 0, 0, 0);

    // 12) combine
    final_kernel<<<(S * H) / 256, 256>>>(x2, eo, wexp, sm, sgl, out);
}